// round 1
// baseline (speedup 1.0000x reference)
#include <cuda_runtime.h>
#include <cstdint>

#define B_  512
#define T_  64
#define E_  300
#define H_  512
#define G_  1536   /* 3*H */

// ---------------- scratch (device globals; no runtime allocation) ----------
__device__ float g_x   [(size_t)B_ * T_ * E_];        // [t*B+b][E]
__device__ float g_gx0 [(size_t)B_ * T_ * 2 * G_];    // [t*B+b][3072] (fwd|bwd)
__device__ float g_h1  [(size_t)B_ * T_ * 2 * H_];    // [t*B+b][1024] layer0 out
__device__ float g_gx1 [(size_t)B_ * T_ * G_];        // [t*B+b][1536] layer1 fwd gx
__device__ float g_gx1b[(size_t)B_ * G_];             // layer1 bwd gx (t=T-1 only)
__device__ float g_h   [2 * 2 * B_ * H_];             // [buf][dir][b][h] ping-pong
__device__ float g_lastb[(size_t)B_ * H_];            // layer1 bwd output @ t=T-1

// ---------------- helpers ---------------------------------------------------
__device__ __forceinline__ float sigm(float x) {
    return __fdividef(1.f, 1.f + __expf(-x));
}
__device__ __forceinline__ float tanh_(float x) {
    return 2.f * sigm(2.f * x) - 1.f;
}

// ---------------- embedding gather -----------------------------------------
__global__ void embed_kernel(const int* __restrict__ tokens,
                             const float* __restrict__ emb,
                             float* __restrict__ x)
{
    const int blk = blockIdx.x;          // blk = t*B + b
    const int t = blk / B_;
    const int b = blk - t * B_;
    const int tok = tokens[b * T_ + t];
    const float* src = emb + (size_t)tok * E_;
    float* dst = x + (size_t)blk * E_;
    for (int e = threadIdx.x; e < E_; e += blockDim.x) dst[e] = src[e];
}

__global__ void zero_kernel(float* __restrict__ p, int n)
{
    int i = blockIdx.x * blockDim.x + threadIdx.x;
    if (i < n) p[i] = 0.f;
}

// ---------------- generic fp32 GEMM: C[M,N] = A[M,K] @ W[N,K]^T + bias[N] ---
// BM=128, BN=64, BK=16, 256 threads, 8x4 per-thread tile. M%128==0, N%64==0.
__global__ void __launch_bounds__(256)
gemm_atb_bias(const float* __restrict__ A, const float* __restrict__ W,
              const float* __restrict__ bias, float* __restrict__ C,
              int M, int N, int K)
{
    const int BM = 128, BN = 64, BK = 16;
    __shared__ float shA[128][17];
    __shared__ float shB[64][17];

    const int m0 = blockIdx.y * BM;
    const int n0 = blockIdx.x * BN;
    const int tid = threadIdx.x;
    const int tx = tid & 15;   // 16 col groups of 4
    const int ty = tid >> 4;   // 16 row groups of 8

    float acc[8][4];
    #pragma unroll
    for (int i = 0; i < 8; i++)
        #pragma unroll
        for (int j = 0; j < 4; j++) acc[i][j] = 0.f;

    for (int k0 = 0; k0 < K; k0 += BK) {
        #pragma unroll
        for (int l = 0; l < (BM * BK) / 256; l++) {           // 8
            int idx = tid + l * 256;
            int r = idx >> 4, kk = idx & 15;
            int k = k0 + kk;
            shA[r][kk] = (k < K) ? A[(size_t)(m0 + r) * K + k] : 0.f;
        }
        #pragma unroll
        for (int l = 0; l < (BN * BK) / 256; l++) {           // 4
            int idx = tid + l * 256;
            int r = idx >> 4, kk = idx & 15;
            int k = k0 + kk;
            shB[r][kk] = (k < K) ? W[(size_t)(n0 + r) * K + k] : 0.f;
        }
        __syncthreads();
        #pragma unroll
        for (int kk = 0; kk < BK; kk++) {
            float a[8], b[4];
            #pragma unroll
            for (int i = 0; i < 8; i++) a[i] = shA[ty * 8 + i][kk];
            #pragma unroll
            for (int j = 0; j < 4; j++) b[j] = shB[tx * 4 + j][kk];
            #pragma unroll
            for (int i = 0; i < 8; i++)
                #pragma unroll
                for (int j = 0; j < 4; j++)
                    acc[i][j] += a[i] * b[j];
        }
        __syncthreads();
    }
    #pragma unroll
    for (int i = 0; i < 8; i++) {
        int m = m0 + ty * 8 + i;
        #pragma unroll
        for (int j = 0; j < 4; j++) {
            int n = n0 + tx * 4 + j;
            C[(size_t)m * N + n] = acc[i][j] + bias[n];
        }
    }
}

// ---------------- fused GRU step: gh GEMM (B x 48-col tile, K=512) + gates --
// grid: (B/64, H/16, ndir). 128 threads. Tile = 64 batch rows x 16 hidden
// units x 3 gates. Writes h_next and (optionally) the h1 history slice.
__global__ void __launch_bounds__(128)
gru_step(const float* __restrict__ h_prev,   // [ndir][B][H]
         float* __restrict__ h_next,         // [ndir][B][H]
         const float* __restrict__ gx,       // [T*B][gx_ld]
         int gx_ld, int gx_dir_stride,       // col offset per dir
         const float* __restrict__ Whh,      // [ndir][G][H]
         const float* __restrict__ bhh,      // [ndir][G]
         float* __restrict__ y,              // [T*B][1024] or nullptr
         int s)
{
    const int BK = 16;
    const int d  = blockIdx.z;
    const int b0 = blockIdx.x * 64;
    const int j0 = blockIdx.y * 16;
    const int t  = (d == 0) ? s : (T_ - 1 - s);
    const int tid = threadIdx.x;

    __shared__ float shH[64][17];
    __shared__ float shW[48][17];
    __shared__ float shG[64][49];

    const float* hp_base = h_prev + (size_t)d * B_ * H_;
    const float* W_base  = Whh + (size_t)d * G_ * H_;
    const float* bhh_d   = bhh + (size_t)d * G_;

    const int tx = tid & 7;    // 8 col groups of 6
    const int ty = tid >> 3;   // 16 row groups of 4

    float acc[4][6];
    #pragma unroll
    for (int i = 0; i < 4; i++)
        #pragma unroll
        for (int j = 0; j < 6; j++) acc[i][j] = 0.f;

    for (int k0 = 0; k0 < H_; k0 += BK) {
        #pragma unroll
        for (int l = 0; l < (64 * BK) / 128; l++) {            // 8
            int idx = tid + l * 128;
            int r = idx >> 4, kk = idx & 15;
            shH[r][kk] = hp_base[(size_t)(b0 + r) * H_ + k0 + kk];
        }
        #pragma unroll
        for (int l = 0; l < (48 * BK) / 128; l++) {            // 6
            int idx = tid + l * 128;
            int c = idx >> 4, kk = idx & 15;
            int gate = c >> 4, jj = c & 15;
            int g = gate * H_ + j0 + jj;
            shW[c][kk] = W_base[(size_t)g * H_ + k0 + kk];
        }
        __syncthreads();
        #pragma unroll
        for (int kk = 0; kk < BK; kk++) {
            float a[4], b[6];
            #pragma unroll
            for (int i = 0; i < 4; i++) a[i] = shH[ty * 4 + i][kk];
            #pragma unroll
            for (int j = 0; j < 6; j++) b[j] = shW[tx * 6 + j][kk];
            #pragma unroll
            for (int i = 0; i < 4; i++)
                #pragma unroll
                for (int j = 0; j < 6; j++)
                    acc[i][j] += a[i] * b[j];
        }
        __syncthreads();
    }

    // gh tile (+ recurrent bias) -> shared
    #pragma unroll
    for (int i = 0; i < 4; i++) {
        int r = ty * 4 + i;
        #pragma unroll
        for (int j = 0; j < 6; j++) {
            int c = tx * 6 + j;
            int gate = c >> 4, jj = c & 15;
            shG[r][c] = acc[i][j] + bhh_d[gate * H_ + j0 + jj];
        }
    }
    __syncthreads();

    // gate math: 64 rows x 16 units
    #pragma unroll
    for (int l = 0; l < (64 * 16) / 128; l++) {                // 8
        int u  = tid + l * 128;
        int jj = u & 15;
        int rr = u >> 4;
        int b  = b0 + rr;
        int j  = j0 + jj;
        size_t row = (size_t)t * B_ + b;
        const float* gxr = gx + row * gx_ld + (size_t)d * gx_dir_stride;
        float xr = gxr[j];
        float xz = gxr[H_ + j];
        float xn = gxr[2 * H_ + j];
        float ghr = shG[rr][jj];
        float ghz = shG[rr][16 + jj];
        float ghn = shG[rr][32 + jj];
        float rg = sigm(xr + ghr);
        float zg = sigm(xz + ghz);
        float ng = tanh_(xn + rg * ghn);
        float hp = hp_base[(size_t)b * H_ + j];
        float hn = (1.f - zg) * ng + zg * hp;
        h_next[((size_t)d * B_ + b) * H_ + j] = hn;
        if (y) y[row * (2 * H_) + (size_t)d * H_ + j] = hn;
    }
}

// ---------------- layer-1 backward collapses to a single step (h0 = 0) -----
__global__ void bwd1_gates(const float* __restrict__ gxb,    // [B][1536]
                           const float* __restrict__ bhh,    // [1536] (dir 1)
                           float* __restrict__ out)          // [B][512]
{
    int idx = blockIdx.x * blockDim.x + threadIdx.x;
    if (idx >= B_ * H_) return;
    int b = idx >> 9;
    int j = idx & 511;
    const float* r0 = gxb + (size_t)b * G_;
    float rg = sigm(r0[j] + bhh[j]);
    float zg = sigm(r0[H_ + j] + bhh[H_ + j]);
    float ng = tanh_(r0[2 * H_ + j] + rg * bhh[2 * H_ + j]);
    out[idx] = (1.f - zg) * ng;   // (1-z)*n + z*0
}

// ---------------- final FC: out[b][o] = last[b] . fc_w[o] + fc_b[o] --------
__global__ void fc_kernel(const float* __restrict__ hf,     // [B][512]
                          const float* __restrict__ hb,     // [B][512]
                          const float* __restrict__ fcw,    // [2][1024]
                          const float* __restrict__ fcb,    // [2]
                          float* __restrict__ out)          // [B][2]
{
    int b = blockIdx.x;
    int tid = threadIdx.x;   // 256
    float s0 = 0.f, s1 = 0.f;
    for (int j = tid; j < 1024; j += 256) {
        float v = (j < 512) ? hf[(size_t)b * 512 + j]
                            : hb[(size_t)b * 512 + (j - 512)];
        s0 += v * fcw[j];
        s1 += v * fcw[1024 + j];
    }
    __shared__ float red0[256];
    __shared__ float red1[256];
    red0[tid] = s0; red1[tid] = s1;
    __syncthreads();
    for (int off = 128; off > 0; off >>= 1) {
        if (tid < off) { red0[tid] += red0[tid + off]; red1[tid] += red1[tid + off]; }
        __syncthreads();
    }
    if (tid == 0) {
        out[b * 2 + 0] = red0[0] + fcb[0];
        out[b * 2 + 1] = red1[0] + fcb[1];
    }
}

// ---------------- launch ----------------------------------------------------
extern "C" void kernel_launch(void* const* d_in, const int* in_sizes, int n_in,
                              void* d_out, int out_size)
{
    (void)in_sizes; (void)n_in; (void)out_size;
    const int*   tokens = (const int*)  d_in[0];
    const float* emb    = (const float*)d_in[1];
    const float* w_ih0  = (const float*)d_in[2];
    const float* w_hh0  = (const float*)d_in[3];
    const float* b_ih0  = (const float*)d_in[4];
    const float* b_hh0  = (const float*)d_in[5];
    const float* w_ih1  = (const float*)d_in[6];
    const float* w_hh1  = (const float*)d_in[7];
    const float* b_ih1  = (const float*)d_in[8];
    const float* b_hh1  = (const float*)d_in[9];
    const float* fc_w   = (const float*)d_in[10];
    const float* fc_b   = (const float*)d_in[11];
    float* out = (float*)d_out;

    float *px, *pgx0, *ph1, *pgx1, *pgx1b, *ph, *plastb;
    cudaGetSymbolAddress((void**)&px,     g_x);
    cudaGetSymbolAddress((void**)&pgx0,   g_gx0);
    cudaGetSymbolAddress((void**)&ph1,    g_h1);
    cudaGetSymbolAddress((void**)&pgx1,   g_gx1);
    cudaGetSymbolAddress((void**)&pgx1b,  g_gx1b);
    cudaGetSymbolAddress((void**)&ph,     g_h);
    cudaGetSymbolAddress((void**)&plastb, g_lastb);

    const int HBUF = 2 * B_ * H_;   // one ping-pong buffer (2 dirs)

    // 1) embedding gather, x[t*B+b][E]
    embed_kernel<<<B_ * T_, 128>>>(tokens, emb, px);

    // 2) h := 0
    zero_kernel<<<(2 * HBUF + 255) / 256, 256>>>(ph, 2 * HBUF);

    // 3) layer0 input GEMM, both dirs fused: gx0[32768][3072]
    gemm_atb_bias<<<dim3(2 * G_ / 64, (B_ * T_) / 128), 256>>>(
        px, w_ih0, b_ih0, pgx0, B_ * T_, 2 * G_, E_);

    // 4) layer0 bidirectional scan (64 sequential steps, 2 dirs in parallel)
    for (int s = 0; s < T_; s++) {
        int pb = s & 1;
        gru_step<<<dim3(B_ / 64, H_ / 16, 2), 128>>>(
            ph + pb * HBUF, ph + (pb ^ 1) * HBUF,
            pgx0, 2 * G_, G_, w_hh0, b_hh0, ph1, s);
    }

    // 5) layer1 fwd input GEMM: gx1[32768][1536]
    gemm_atb_bias<<<dim3(G_ / 64, (B_ * T_) / 128), 256>>>(
        ph1, w_ih1, b_ih1, pgx1, B_ * T_, G_, 2 * H_);

    // 6) h := 0 again, then layer1 forward scan (only final hidden needed)
    zero_kernel<<<(2 * HBUF + 255) / 256, 256>>>(ph, 2 * HBUF);
    for (int s = 0; s < T_; s++) {
        int pb = s & 1;
        gru_step<<<dim3(B_ / 64, H_ / 16, 1), 128>>>(
            ph + pb * HBUF, ph + (pb ^ 1) * HBUF,
            pgx1, G_, 0, w_hh1, b_hh1, nullptr, s);
    }
    // final fwd hidden now in buffer 0, dir 0 (64 steps: ends in buf 0)

    // 7) layer1 backward = exactly ONE GRU step on h1[:, T-1] with h0=0
    gemm_atb_bias<<<dim3(G_ / 64, B_ / 128), 256>>>(
        ph1 + (size_t)(T_ - 1) * B_ * (2 * H_),
        w_ih1 + (size_t)G_ * (2 * H_), b_ih1 + G_,
        pgx1b, B_, G_, 2 * H_);
    bwd1_gates<<<(B_ * H_ + 255) / 256, 256>>>(pgx1b, b_hh1 + G_, plastb);

    // 8) FC head
    fc_kernel<<<B_, 256>>>(ph, plastb, fc_w, fc_b, out);
}

// round 2
// speedup vs baseline: 1.0027x; 1.0027x over previous
#include <cuda_runtime.h>
#include <cstdint>

#define B_  512
#define T_  64
#define E_  300
#define H_  512
#define G_  1536   /* 3*H */

// ---------------- scratch (device globals; no runtime allocation) ----------
__device__ float g_x   [(size_t)B_ * T_ * E_];        // [t*B+b][E]
__device__ float g_gx0 [(size_t)B_ * T_ * 2 * G_];    // [t*B+b][3072] (fwd|bwd)
__device__ float g_h1  [(size_t)B_ * T_ * 2 * H_];    // [t*B+b][1024] layer0 out
__device__ float g_gx1 [(size_t)B_ * T_ * G_];        // [t*B+b][1536] layer1 fwd gx
__device__ float g_gx1b[(size_t)B_ * G_];             // layer1 bwd gx (t=T-1 only)
__device__ float g_h   [2 * 2 * B_ * H_];             // [buf][dir][b][h] ping-pong
__device__ float g_lastb[(size_t)B_ * H_];            // layer1 bwd output @ t=T-1

// ---------------- helpers ---------------------------------------------------
__device__ __forceinline__ float sigm(float x) {
    return __fdividef(1.f, 1.f + __expf(-x));
}
__device__ __forceinline__ float tanh_(float x) {
    return 2.f * sigm(2.f * x) - 1.f;
}

// ---------------- embedding gather -----------------------------------------
__global__ void embed_kernel(const int* __restrict__ tokens,
                             const float* __restrict__ emb,
                             float* __restrict__ x)
{
    const int blk = blockIdx.x;          // blk = t*B + b
    const int t = blk / B_;
    const int b = blk - t * B_;
    const int tok = tokens[b * T_ + t];
    const float* src = emb + (size_t)tok * E_;
    float* dst = x + (size_t)blk * E_;
    for (int e = threadIdx.x; e < E_; e += blockDim.x) dst[e] = src[e];
}

__global__ void zero_kernel(float* __restrict__ p, int n)
{
    int i = blockIdx.x * blockDim.x + threadIdx.x;
    if (i < n) p[i] = 0.f;
}

// ---------------- generic fp32 GEMM: C[M,N] = A[M,K] @ W[N,K]^T + bias[N] ---
// BM=128, BN=64, BK=16, 256 threads, 8x4 per-thread tile. M%128==0, N%64==0.
__global__ void __launch_bounds__(256)
gemm_atb_bias(const float* __restrict__ A, const float* __restrict__ W,
              const float* __restrict__ bias, float* __restrict__ C,
              int M, int N, int K)
{
    const int BM = 128, BN = 64, BK = 16;
    __shared__ float shA[128][17];
    __shared__ float shB[64][17];

    const int m0 = blockIdx.y * BM;
    const int n0 = blockIdx.x * BN;
    const int tid = threadIdx.x;
    const int tx = tid & 15;   // 16 col groups of 4
    const int ty = tid >> 4;   // 16 row groups of 8

    float acc[8][4];
    #pragma unroll
    for (int i = 0; i < 8; i++)
        #pragma unroll
        for (int j = 0; j < 4; j++) acc[i][j] = 0.f;

    for (int k0 = 0; k0 < K; k0 += BK) {
        #pragma unroll
        for (int l = 0; l < (BM * BK) / 256; l++) {           // 8
            int idx = tid + l * 256;
            int r = idx >> 4, kk = idx & 15;
            int k = k0 + kk;
            shA[r][kk] = (k < K) ? A[(size_t)(m0 + r) * K + k] : 0.f;
        }
        #pragma unroll
        for (int l = 0; l < (BN * BK) / 256; l++) {           // 4
            int idx = tid + l * 256;
            int r = idx >> 4, kk = idx & 15;
            int k = k0 + kk;
            shB[r][kk] = (k < K) ? W[(size_t)(n0 + r) * K + k] : 0.f;
        }
        __syncthreads();
        #pragma unroll
        for (int kk = 0; kk < BK; kk++) {
            float a[8], b[4];
            #pragma unroll
            for (int i = 0; i < 8; i++) a[i] = shA[ty * 8 + i][kk];
            #pragma unroll
            for (int j = 0; j < 4; j++) b[j] = shB[tx * 4 + j][kk];
            #pragma unroll
            for (int i = 0; i < 8; i++)
                #pragma unroll
                for (int j = 0; j < 4; j++)
                    acc[i][j] += a[i] * b[j];
        }
        __syncthreads();
    }
    #pragma unroll
    for (int i = 0; i < 8; i++) {
        int m = m0 + ty * 8 + i;
        #pragma unroll
        for (int j = 0; j < 4; j++) {
            int n = n0 + tx * 4 + j;
            C[(size_t)m * N + n] = acc[i][j] + bias[n];
        }
    }
}

// ---------------- fused GRU step: gh GEMM (B x 48-col tile, K=512) + gates --
// grid: (B/64, H/16, ndir). 128 threads. Tile = 64 batch rows x 16 hidden
// units x 3 gates. Writes h_next and (optionally) the h1 history slice.
__global__ void __launch_bounds__(128)
gru_step(const float* __restrict__ h_prev,   // [ndir][B][H]
         float* __restrict__ h_next,         // [ndir][B][H]
         const float* __restrict__ gx,       // [T*B][gx_ld]
         int gx_ld, int gx_dir_stride,       // col offset per dir
         const float* __restrict__ Whh,      // [ndir][G][H]
         const float* __restrict__ bhh,      // [ndir][G]
         float* __restrict__ y,              // [T*B][1024] or nullptr
         int s)
{
    const int BK = 16;
    const int d  = blockIdx.z;
    const int b0 = blockIdx.x * 64;
    const int j0 = blockIdx.y * 16;
    const int t  = (d == 0) ? s : (T_ - 1 - s);
    const int tid = threadIdx.x;

    __shared__ float shH[64][17];
    __shared__ float shW[48][17];
    __shared__ float shG[64][49];

    const float* hp_base = h_prev + (size_t)d * B_ * H_;
    const float* W_base  = Whh + (size_t)d * G_ * H_;
    const float* bhh_d   = bhh + (size_t)d * G_;

    const int tx = tid & 7;    // 8 col groups of 6
    const int ty = tid >> 3;   // 16 row groups of 4

    float acc[4][6];
    #pragma unroll
    for (int i = 0; i < 4; i++)
        #pragma unroll
        for (int j = 0; j < 6; j++) acc[i][j] = 0.f;

    for (int k0 = 0; k0 < H_; k0 += BK) {
        #pragma unroll
        for (int l = 0; l < (64 * BK) / 128; l++) {            // 8
            int idx = tid + l * 128;
            int r = idx >> 4, kk = idx & 15;
            shH[r][kk] = hp_base[(size_t)(b0 + r) * H_ + k0 + kk];
        }
        #pragma unroll
        for (int l = 0; l < (48 * BK) / 128; l++) {            // 6
            int idx = tid + l * 128;
            int c = idx >> 4, kk = idx & 15;
            int gate = c >> 4, jj = c & 15;
            int g = gate * H_ + j0 + jj;
            shW[c][kk] = W_base[(size_t)g * H_ + k0 + kk];
        }
        __syncthreads();
        #pragma unroll
        for (int kk = 0; kk < BK; kk++) {
            float a[4], b[6];
            #pragma unroll
            for (int i = 0; i < 4; i++) a[i] = shH[ty * 4 + i][kk];
            #pragma unroll
            for (int j = 0; j < 6; j++) b[j] = shW[tx * 6 + j][kk];
            #pragma unroll
            for (int i = 0; i < 4; i++)
                #pragma unroll
                for (int j = 0; j < 6; j++)
                    acc[i][j] += a[i] * b[j];
        }
        __syncthreads();
    }

    // gh tile (+ recurrent bias) -> shared
    #pragma unroll
    for (int i = 0; i < 4; i++) {
        int r = ty * 4 + i;
        #pragma unroll
        for (int j = 0; j < 6; j++) {
            int c = tx * 6 + j;
            int gate = c >> 4, jj = c & 15;
            shG[r][c] = acc[i][j] + bhh_d[gate * H_ + j0 + jj];
        }
    }
    __syncthreads();

    // gate math: 64 rows x 16 units
    #pragma unroll
    for (int l = 0; l < (64 * 16) / 128; l++) {                // 8
        int u  = tid + l * 128;
        int jj = u & 15;
        int rr = u >> 4;
        int b  = b0 + rr;
        int j  = j0 + jj;
        size_t row = (size_t)t * B_ + b;
        const float* gxr = gx + row * gx_ld + (size_t)d * gx_dir_stride;
        float xr = gxr[j];
        float xz = gxr[H_ + j];
        float xn = gxr[2 * H_ + j];
        float ghr = shG[rr][jj];
        float ghz = shG[rr][16 + jj];
        float ghn = shG[rr][32 + jj];
        float rg = sigm(xr + ghr);
        float zg = sigm(xz + ghz);
        float ng = tanh_(xn + rg * ghn);
        float hp = hp_base[(size_t)b * H_ + j];
        float hn = (1.f - zg) * ng + zg * hp;
        h_next[((size_t)d * B_ + b) * H_ + j] = hn;
        if (y) y[row * (2 * H_) + (size_t)d * H_ + j] = hn;
    }
}

// ---------------- layer-1 backward collapses to a single step (h0 = 0) -----
__global__ void bwd1_gates(const float* __restrict__ gxb,    // [B][1536]
                           const float* __restrict__ bhh,    // [1536] (dir 1)
                           float* __restrict__ out)          // [B][512]
{
    int idx = blockIdx.x * blockDim.x + threadIdx.x;
    if (idx >= B_ * H_) return;
    int b = idx >> 9;
    int j = idx & 511;
    const float* r0 = gxb + (size_t)b * G_;
    float rg = sigm(r0[j] + bhh[j]);
    float zg = sigm(r0[H_ + j] + bhh[H_ + j]);
    float ng = tanh_(r0[2 * H_ + j] + rg * bhh[2 * H_ + j]);
    out[idx] = (1.f - zg) * ng;   // (1-z)*n + z*0
}

// ---------------- final FC: out[b][o] = last[b] . fc_w[o] + fc_b[o] --------
__global__ void fc_kernel(const float* __restrict__ hf,     // [B][512]
                          const float* __restrict__ hb,     // [B][512]
                          const float* __restrict__ fcw,    // [2][1024]
                          const float* __restrict__ fcb,    // [2]
                          float* __restrict__ out)          // [B][2]
{
    int b = blockIdx.x;
    int tid = threadIdx.x;   // 256
    float s0 = 0.f, s1 = 0.f;
    for (int j = tid; j < 1024; j += 256) {
        float v = (j < 512) ? hf[(size_t)b * 512 + j]
                            : hb[(size_t)b * 512 + (j - 512)];
        s0 += v * fcw[j];
        s1 += v * fcw[1024 + j];
    }
    __shared__ float red0[256];
    __shared__ float red1[256];
    red0[tid] = s0; red1[tid] = s1;
    __syncthreads();
    for (int off = 128; off > 0; off >>= 1) {
        if (tid < off) { red0[tid] += red0[tid + off]; red1[tid] += red1[tid + off]; }
        __syncthreads();
    }
    if (tid == 0) {
        out[b * 2 + 0] = red0[0] + fcb[0];
        out[b * 2 + 1] = red1[0] + fcb[1];
    }
}

// ---------------- launch ----------------------------------------------------
extern "C" void kernel_launch(void* const* d_in, const int* in_sizes, int n_in,
                              void* d_out, int out_size)
{
    (void)in_sizes; (void)n_in; (void)out_size;
    const int*   tokens = (const int*)  d_in[0];
    const float* emb    = (const float*)d_in[1];
    const float* w_ih0  = (const float*)d_in[2];
    const float* w_hh0  = (const float*)d_in[3];
    const float* b_ih0  = (const float*)d_in[4];
    const float* b_hh0  = (const float*)d_in[5];
    const float* w_ih1  = (const float*)d_in[6];
    const float* w_hh1  = (const float*)d_in[7];
    const float* b_ih1  = (const float*)d_in[8];
    const float* b_hh1  = (const float*)d_in[9];
    const float* fc_w   = (const float*)d_in[10];
    const float* fc_b   = (const float*)d_in[11];
    float* out = (float*)d_out;

    float *px, *pgx0, *ph1, *pgx1, *pgx1b, *ph, *plastb;
    cudaGetSymbolAddress((void**)&px,     g_x);
    cudaGetSymbolAddress((void**)&pgx0,   g_gx0);
    cudaGetSymbolAddress((void**)&ph1,    g_h1);
    cudaGetSymbolAddress((void**)&pgx1,   g_gx1);
    cudaGetSymbolAddress((void**)&pgx1b,  g_gx1b);
    cudaGetSymbolAddress((void**)&ph,     g_h);
    cudaGetSymbolAddress((void**)&plastb, g_lastb);

    const int HBUF = 2 * B_ * H_;   // one ping-pong buffer (2 dirs)

    // 1) embedding gather, x[t*B+b][E]
    embed_kernel<<<B_ * T_, 128>>>(tokens, emb, px);

    // 2) h := 0
    zero_kernel<<<(2 * HBUF + 255) / 256, 256>>>(ph, 2 * HBUF);

    // 3) layer0 input GEMM, both dirs fused: gx0[32768][3072]
    gemm_atb_bias<<<dim3(2 * G_ / 64, (B_ * T_) / 128), 256>>>(
        px, w_ih0, b_ih0, pgx0, B_ * T_, 2 * G_, E_);

    // 4) layer0 bidirectional scan (64 sequential steps, 2 dirs in parallel)
    for (int s = 0; s < T_; s++) {
        int pb = s & 1;
        gru_step<<<dim3(B_ / 64, H_ / 16, 2), 128>>>(
            ph + pb * HBUF, ph + (pb ^ 1) * HBUF,
            pgx0, 2 * G_, G_, w_hh0, b_hh0, ph1, s);
    }

    // 5) layer1 fwd input GEMM: gx1[32768][1536]
    gemm_atb_bias<<<dim3(G_ / 64, (B_ * T_) / 128), 256>>>(
        ph1, w_ih1, b_ih1, pgx1, B_ * T_, G_, 2 * H_);

    // 6) h := 0 again, then layer1 forward scan (only final hidden needed)
    zero_kernel<<<(2 * HBUF + 255) / 256, 256>>>(ph, 2 * HBUF);
    for (int s = 0; s < T_; s++) {
        int pb = s & 1;
        gru_step<<<dim3(B_ / 64, H_ / 16, 1), 128>>>(
            ph + pb * HBUF, ph + (pb ^ 1) * HBUF,
            pgx1, G_, 0, w_hh1, b_hh1, nullptr, s);
    }
    // final fwd hidden now in buffer 0, dir 0 (64 steps: ends in buf 0)

    // 7) layer1 backward = exactly ONE GRU step on h1[:, T-1] with h0=0
    gemm_atb_bias<<<dim3(G_ / 64, B_ / 128), 256>>>(
        ph1 + (size_t)(T_ - 1) * B_ * (2 * H_),
        w_ih1 + (size_t)G_ * (2 * H_), b_ih1 + G_,
        pgx1b, B_, G_, 2 * H_);
    bwd1_gates<<<(B_ * H_ + 255) / 256, 256>>>(pgx1b, b_hh1 + G_, plastb);

    // 8) FC head
    fc_kernel<<<B_, 256>>>(ph, plastb, fc_w, fc_b, out);
}

// round 4
// speedup vs baseline: 1.3722x; 1.3684x over previous
#include <cuda_runtime.h>
#include <cuda_bf16.h>
#include <cstdint>

#define B_  512
#define T_  64
#define H_  512
#define G_  1536
#define KP0 320

// ---------------- scratch ----------------------------------------------------
__device__ float g_gx0 [(size_t)B_ * T_ * 2 * G_];
__device__ float g_h1  [(size_t)B_ * T_ * 2 * H_];
__device__ float g_gx1 [(size_t)B_ * T_ * G_];
__device__ float g_gx1b[(size_t)B_ * G_];
__device__ float g_h   [2 * 2 * B_ * H_];
__device__ float g_lastb[(size_t)B_ * H_];
__device__ __align__(16) __nv_bfloat16 g_a0hi[(size_t)B_ * T_ * KP0];
__device__ __align__(16) __nv_bfloat16 g_a0lo[(size_t)B_ * T_ * KP0];
__device__ __align__(16) __nv_bfloat16 g_w0hi[(size_t)2 * G_ * KP0];
__device__ __align__(16) __nv_bfloat16 g_w0lo[(size_t)2 * G_ * KP0];
__device__ __align__(16) __nv_bfloat16 g_a1hi[(size_t)B_ * T_ * 2 * H_];
__device__ __align__(16) __nv_bfloat16 g_a1lo[(size_t)B_ * T_ * 2 * H_];
__device__ __align__(16) __nv_bfloat16 g_w1hi[(size_t)2 * G_ * 2 * H_];
__device__ __align__(16) __nv_bfloat16 g_w1lo[(size_t)2 * G_ * 2 * H_];

// ---------------- baseline-PTX helpers (NO sm_103a-only features) ----------
__device__ __forceinline__ uint32_t smem_u32(const void* p) {
    uint32_t a;
    asm("{ .reg .u64 t; cvta.to.shared.u64 t, %1; cvt.u32.u64 %0, t; }" : "=r"(a) : "l"(p));
    return a;
}
#define CP16(sm, gp)  asm volatile("cp.async.cg.shared.global [%0], [%1], 16;" :: "r"(sm), "l"(gp))
#define CP_COMMIT()   asm volatile("cp.async.commit_group;" ::: "memory")
#define CP_WAIT(n)    asm volatile("cp.async.wait_group %0;" :: "n"(n) : "memory")

__device__ __forceinline__ void ldsm4(uint32_t* r, uint32_t a) {
    asm volatile("ldmatrix.sync.aligned.m8n8.x4.shared.b16 {%0,%1,%2,%3}, [%4];"
        : "=r"(r[0]), "=r"(r[1]), "=r"(r[2]), "=r"(r[3]) : "r"(a));
}
__device__ __forceinline__ void ldsm2(uint32_t* r, uint32_t a) {
    asm volatile("ldmatrix.sync.aligned.m8n8.x2.shared.b16 {%0,%1}, [%2];"
        : "=r"(r[0]), "=r"(r[1]) : "r"(a));
}
__device__ __forceinline__ void mma16816(float* c, const uint32_t* a, const uint32_t* b) {
    asm volatile("mma.sync.aligned.m16n8k16.row.col.f32.bf16.bf16.f32 "
        "{%0,%1,%2,%3},{%4,%5,%6,%7},{%8,%9},{%0,%1,%2,%3};"
        : "+f"(c[0]), "+f"(c[1]), "+f"(c[2]), "+f"(c[3])
        : "r"(a[0]), "r"(a[1]), "r"(a[2]), "r"(a[3]), "r"(b[0]), "r"(b[1]));
}

__device__ __forceinline__ float sigm(float x) { return __fdividef(1.f, 1.f + __expf(-x)); }
__device__ __forceinline__ float tanh_(float x) { return 2.f * sigm(2.f * x) - 1.f; }

// ---------------- split kernels ---------------------------------------------
__global__ void embed_split_kernel(const int* __restrict__ tokens,
                                   const float* __restrict__ emb,
                                   __nv_bfloat16* __restrict__ hi,
                                   __nv_bfloat16* __restrict__ lo)
{
    const int blk = blockIdx.x;
    const int t = blk / B_;
    const int b = blk - t * B_;
    const int tok = tokens[b * T_ + t];
    const float* src = emb + (size_t)tok * 300;
    size_t dst = (size_t)blk * KP0;
    for (int e = threadIdx.x; e < KP0; e += blockDim.x) {
        float v = (e < 300) ? src[e] : 0.f;
        __nv_bfloat16 h = __float2bfloat16(v);
        hi[dst + e] = h;
        lo[dst + e] = __float2bfloat16(v - __bfloat162float(h));
    }
}

__global__ void split_pad_kernel(const float* __restrict__ src,
                                 __nv_bfloat16* __restrict__ hi,
                                 __nv_bfloat16* __restrict__ lo,
                                 int rows, int K, int Kp)
{
    size_t idx = (size_t)blockIdx.x * blockDim.x + threadIdx.x;
    if (idx >= (size_t)rows * Kp) return;
    int r = (int)(idx / Kp);
    int c = (int)(idx - (size_t)r * Kp);
    float v = (c < K) ? src[(size_t)r * K + c] : 0.f;
    __nv_bfloat16 h = __float2bfloat16(v);
    hi[idx] = h;
    lo[idx] = __float2bfloat16(v - __bfloat162float(h));
}

__global__ void zero_kernel(float* __restrict__ p, int n)
{
    int i = blockIdx.x * blockDim.x + threadIdx.x;
    if (i < n) p[i] = 0.f;
}

// ---------------- warp-MMA bf16-split GEMM ----------------------------------
// C[M,N] = (Ahi+Alo)[M,Kp] @ (Whi+Wlo)[N,Kp]^T + bias  (AhiWhi+AhiWlo+AloWhi)
// CTA tile 128x128, 8 warps (2m x 4n), warp tile 64x32, K-chunk 32, cp.async x2.
#define SSTR 80            /* smem row stride bytes (40 bf16): conflict-free */
#define TILE_B (128 * SSTR)
#define STAGE_B (4 * TILE_B)
__global__ void __launch_bounds__(256, 1)
gemm_mma_split(const __nv_bfloat16* __restrict__ Ahi,
               const __nv_bfloat16* __restrict__ Alo,
               const __nv_bfloat16* __restrict__ Whi,
               const __nv_bfloat16* __restrict__ Wlo,
               const float* __restrict__ bias,
               float* __restrict__ C, int N, int Kp)
{
    extern __shared__ __align__(16) char smem[];
    const int tid = threadIdx.x;
    const int lane = tid & 31;
    const int wid = tid >> 5;
    const int wm = wid & 1;          // 2 warps in M
    const int wn = wid >> 1;         // 4 warps in N
    const int m0c = blockIdx.y * 128;
    const int n0c = blockIdx.x * 128;
    const int nchunks = Kp >> 5;
    const uint32_t sbase = smem_u32(smem);

    const __nv_bfloat16* bases[4] = { Ahi, Alo, Whi, Wlo };

    // per-chunk cp.async load: 4 tiles x 128 rows x 64B
    auto load_chunk = [&](int c, int s) {
        const uint32_t st = sbase + s * STAGE_B;
        #pragma unroll
        for (int q = 0; q < 8; q++) {
            int g = tid + q * 256;
            int tile = g >> 9;
            int p = g & 511;
            int r = p >> 2, seg = p & 3;
            int rowbase = (tile < 2) ? m0c : n0c;
            const __nv_bfloat16* gp =
                bases[tile] + (size_t)(rowbase + r) * Kp + c * 32 + seg * 8;
            CP16(st + tile * TILE_B + r * SSTR + seg * 16, gp);
        }
        CP_COMMIT();
    };

    float acc[16][4];
    #pragma unroll
    for (int i = 0; i < 16; i++)
        #pragma unroll
        for (int j = 0; j < 4; j++) acc[i][j] = 0.f;

    load_chunk(0, 0);
    for (int c = 0; c < nchunks; c++) {
        const int s = c & 1;
        if (c + 1 < nchunks) { load_chunk(c + 1, s ^ 1); CP_WAIT(1); }
        else                 { CP_WAIT(0); }
        __syncthreads();
        const uint32_t st = sbase + s * STAGE_B;
        #pragma unroll
        for (int kk = 0; kk < 2; kk++) {
            uint32_t ahi[4][4], alo[4][4], bhi[4][2], blo[4][2];
            #pragma unroll
            for (int i = 0; i < 4; i++) {
                int row = wm * 64 + i * 16 + (lane & 15);
                uint32_t off = row * SSTR + kk * 32 + (lane >> 4) * 16;
                ldsm4(ahi[i], st + off);
                ldsm4(alo[i], st + TILE_B + off);
            }
            #pragma unroll
            for (int j = 0; j < 4; j++) {
                int row = wn * 32 + j * 8 + (lane & 7);
                uint32_t off = row * SSTR + kk * 32 + ((lane >> 3) & 1) * 16;
                ldsm2(bhi[j], st + 2 * TILE_B + off);
                ldsm2(blo[j], st + 3 * TILE_B + off);
            }
            #pragma unroll
            for (int i = 0; i < 4; i++)
                #pragma unroll
                for (int j = 0; j < 4; j++) {
                    mma16816(acc[i * 4 + j], ahi[i], bhi[j]);
                    mma16816(acc[i * 4 + j], ahi[i], blo[j]);
                    mma16816(acc[i * 4 + j], alo[i], bhi[j]);
                }
        }
        __syncthreads();
    }

    // epilogue: direct float2 stores + bias
    #pragma unroll
    for (int i = 0; i < 4; i++) {
        int m = m0c + wm * 64 + i * 16 + (lane >> 2);
        #pragma unroll
        for (int j = 0; j < 4; j++) {
            int n = n0c + wn * 32 + j * 8 + (lane & 3) * 2;
            float b0 = bias[n], b1 = bias[n + 1];
            float* a = acc[i * 4 + j];
            float2 v0 = { a[0] + b0, a[1] + b1 };
            float2 v1 = { a[2] + b0, a[3] + b1 };
            *reinterpret_cast<float2*>(C + (size_t)m * N + n) = v0;
            *reinterpret_cast<float2*>(C + (size_t)(m + 8) * N + n) = v1;
        }
    }
}

// ---------------- fused GRU step (unchanged, known-good) -------------------
__global__ void __launch_bounds__(128)
gru_step(const float* __restrict__ h_prev, float* __restrict__ h_next,
         const float* __restrict__ gx, int gx_ld, int gx_dir_stride,
         const float* __restrict__ Whh, const float* __restrict__ bhh,
         float* __restrict__ y, int s)
{
    const int BK = 16;
    const int d  = blockIdx.z;
    const int b0 = blockIdx.x * 64;
    const int j0 = blockIdx.y * 16;
    const int t  = (d == 0) ? s : (T_ - 1 - s);
    const int tid = threadIdx.x;

    __shared__ float shH[64][17];
    __shared__ float shW[48][17];
    __shared__ float shG[64][49];

    const float* hp_base = h_prev + (size_t)d * B_ * H_;
    const float* W_base  = Whh + (size_t)d * G_ * H_;
    const float* bhh_d   = bhh + (size_t)d * G_;
    const int tx = tid & 7, ty = tid >> 3;

    float acc[4][6];
    #pragma unroll
    for (int i = 0; i < 4; i++)
        #pragma unroll
        for (int j = 0; j < 6; j++) acc[i][j] = 0.f;

    for (int k0 = 0; k0 < H_; k0 += BK) {
        #pragma unroll
        for (int l = 0; l < 8; l++) {
            int idx = tid + l * 128;
            int r = idx >> 4, kk = idx & 15;
            shH[r][kk] = hp_base[(size_t)(b0 + r) * H_ + k0 + kk];
        }
        #pragma unroll
        for (int l = 0; l < 6; l++) {
            int idx = tid + l * 128;
            int cc = idx >> 4, kk = idx & 15;
            int gate = cc >> 4, jj = cc & 15;
            shW[cc][kk] = W_base[(size_t)(gate * H_ + j0 + jj) * H_ + k0 + kk];
        }
        __syncthreads();
        #pragma unroll
        for (int kk = 0; kk < BK; kk++) {
            float a[4], b[6];
            #pragma unroll
            for (int i = 0; i < 4; i++) a[i] = shH[ty * 4 + i][kk];
            #pragma unroll
            for (int j = 0; j < 6; j++) b[j] = shW[tx * 6 + j][kk];
            #pragma unroll
            for (int i = 0; i < 4; i++)
                #pragma unroll
                for (int j = 0; j < 6; j++) acc[i][j] += a[i] * b[j];
        }
        __syncthreads();
    }
    #pragma unroll
    for (int i = 0; i < 4; i++) {
        int r = ty * 4 + i;
        #pragma unroll
        for (int j = 0; j < 6; j++) {
            int cc = tx * 6 + j;
            int gate = cc >> 4, jj = cc & 15;
            shG[r][cc] = acc[i][j] + bhh_d[gate * H_ + j0 + jj];
        }
    }
    __syncthreads();
    #pragma unroll
    for (int l = 0; l < 8; l++) {
        int u = tid + l * 128;
        int jj = u & 15, rr = u >> 4;
        int b = b0 + rr, j = j0 + jj;
        size_t row = (size_t)t * B_ + b;
        const float* gxr = gx + row * gx_ld + (size_t)d * gx_dir_stride;
        float rg = sigm(gxr[j] + shG[rr][jj]);
        float zg = sigm(gxr[H_ + j] + shG[rr][16 + jj]);
        float ng = tanh_(gxr[2 * H_ + j] + rg * shG[rr][32 + jj]);
        float hp = hp_base[(size_t)b * H_ + j];
        float hn = (1.f - zg) * ng + zg * hp;
        h_next[((size_t)d * B_ + b) * H_ + j] = hn;
        if (y) y[row * (2 * H_) + (size_t)d * H_ + j] = hn;
    }
}

__global__ void bwd1_gates(const float* __restrict__ gxb,
                           const float* __restrict__ bhh,
                           float* __restrict__ out)
{
    int idx = blockIdx.x * blockDim.x + threadIdx.x;
    if (idx >= B_ * H_) return;
    int b = idx >> 9, j = idx & 511;
    const float* r0 = gxb + (size_t)b * G_;
    float rg = sigm(r0[j] + bhh[j]);
    float zg = sigm(r0[H_ + j] + bhh[H_ + j]);
    float ng = tanh_(r0[2 * H_ + j] + rg * bhh[2 * H_ + j]);
    out[idx] = (1.f - zg) * ng;
}

__global__ void fc_kernel(const float* __restrict__ hf, const float* __restrict__ hb,
                          const float* __restrict__ fcw, const float* __restrict__ fcb,
                          float* __restrict__ out)
{
    int b = blockIdx.x, tid = threadIdx.x;
    float s0 = 0.f, s1 = 0.f;
    for (int j = tid; j < 1024; j += 256) {
        float v = (j < 512) ? hf[(size_t)b * 512 + j] : hb[(size_t)b * 512 + (j - 512)];
        s0 += v * fcw[j];
        s1 += v * fcw[1024 + j];
    }
    __shared__ float red0[256], red1[256];
    red0[tid] = s0; red1[tid] = s1;
    __syncthreads();
    for (int off = 128; off > 0; off >>= 1) {
        if (tid < off) { red0[tid] += red0[tid + off]; red1[tid] += red1[tid + off]; }
        __syncthreads();
    }
    if (tid == 0) {
        out[b * 2 + 0] = red0[0] + fcb[0];
        out[b * 2 + 1] = red1[0] + fcb[1];
    }
}

// ---------------- launch -----------------------------------------------------
extern "C" void kernel_launch(void* const* d_in, const int* in_sizes, int n_in,
                              void* d_out, int out_size)
{
    (void)in_sizes; (void)n_in; (void)out_size;
    const int*   tokens = (const int*)  d_in[0];
    const float* emb    = (const float*)d_in[1];
    const float* w_ih0  = (const float*)d_in[2];
    const float* w_hh0  = (const float*)d_in[3];
    const float* b_ih0  = (const float*)d_in[4];
    const float* b_hh0  = (const float*)d_in[5];
    const float* w_ih1  = (const float*)d_in[6];
    const float* w_hh1  = (const float*)d_in[7];
    const float* b_ih1  = (const float*)d_in[8];
    const float* b_hh1  = (const float*)d_in[9];
    const float* fc_w   = (const float*)d_in[10];
    const float* fc_b   = (const float*)d_in[11];
    float* out = (float*)d_out;

    float *pgx0, *ph1, *pgx1, *pgx1b, *ph, *plastb;
    cudaGetSymbolAddress((void**)&pgx0,   g_gx0);
    cudaGetSymbolAddress((void**)&ph1,    g_h1);
    cudaGetSymbolAddress((void**)&pgx1,   g_gx1);
    cudaGetSymbolAddress((void**)&pgx1b,  g_gx1b);
    cudaGetSymbolAddress((void**)&ph,     g_h);
    cudaGetSymbolAddress((void**)&plastb, g_lastb);
    __nv_bfloat16 *pa0hi, *pa0lo, *pw0hi, *pw0lo, *pa1hi, *pa1lo, *pw1hi, *pw1lo;
    cudaGetSymbolAddress((void**)&pa0hi, g_a0hi);
    cudaGetSymbolAddress((void**)&pa0lo, g_a0lo);
    cudaGetSymbolAddress((void**)&pw0hi, g_w0hi);
    cudaGetSymbolAddress((void**)&pw0lo, g_w0lo);
    cudaGetSymbolAddress((void**)&pa1hi, g_a1hi);
    cudaGetSymbolAddress((void**)&pa1lo, g_a1lo);
    cudaGetSymbolAddress((void**)&pw1hi, g_w1hi);
    cudaGetSymbolAddress((void**)&pw1lo, g_w1lo);

    const int GSM = 2 * STAGE_B;   // 81920
    cudaFuncSetAttribute(gemm_mma_split,
                         cudaFuncAttributeMaxDynamicSharedMemorySize, GSM);
    const int HBUF = 2 * B_ * H_;
    const int MT = B_ * T_;

    // 1) embed + splits
    embed_split_kernel<<<MT, 128>>>(tokens, emb, pa0hi, pa0lo);
    split_pad_kernel<<<(2 * G_ * KP0 + 255) / 256, 256>>>(w_ih0, pw0hi, pw0lo, 2 * G_, 300, KP0);
    split_pad_kernel<<<(int)(((size_t)2 * G_ * 1024 + 255) / 256), 256>>>(w_ih1, pw1hi, pw1lo, 2 * G_, 1024, 1024);
    zero_kernel<<<(2 * HBUF + 255) / 256, 256>>>(ph, 2 * HBUF);

    // 2) layer0 input GEMM (tensor cores): gx0[32768][3072]
    gemm_mma_split<<<dim3(2 * G_ / 128, MT / 128), 256, GSM>>>(
        pa0hi, pa0lo, pw0hi, pw0lo, b_ih0, pgx0, 2 * G_, KP0);

    // 3) layer0 bidirectional scan
    for (int s = 0; s < T_; s++) {
        int pb = s & 1;
        gru_step<<<dim3(B_ / 64, H_ / 16, 2), 128>>>(
            ph + pb * HBUF, ph + (pb ^ 1) * HBUF,
            pgx0, 2 * G_, G_, w_hh0, b_hh0, ph1, s);
    }

    // 4) split h1, layer1 fwd input GEMM
    split_pad_kernel<<<(int)(((size_t)MT * 1024 + 255) / 256), 256>>>(ph1, pa1hi, pa1lo, MT, 1024, 1024);
    gemm_mma_split<<<dim3(G_ / 128, MT / 128), 256, GSM>>>(
        pa1hi, pa1lo, pw1hi, pw1lo, b_ih1, pgx1, G_, 1024);

    // 5) layer1 forward scan
    zero_kernel<<<(2 * HBUF + 255) / 256, 256>>>(ph, 2 * HBUF);
    for (int s = 0; s < T_; s++) {
        int pb = s & 1;
        gru_step<<<dim3(B_ / 64, H_ / 16, 1), 128>>>(
            ph + pb * HBUF, ph + (pb ^ 1) * HBUF,
            pgx1, G_, 0, w_hh1, b_hh1, nullptr, s);
    }

    // 6) layer1 backward = ONE step at t=T-1 (h0=0)
    gemm_mma_split<<<dim3(G_ / 128, B_ / 128), 256, GSM>>>(
        pa1hi + (size_t)(T_ - 1) * B_ * 1024, pa1lo + (size_t)(T_ - 1) * B_ * 1024,
        pw1hi + (size_t)G_ * 1024, pw1lo + (size_t)G_ * 1024,
        b_ih1 + G_, pgx1b, G_, 1024);
    bwd1_gates<<<(B_ * H_ + 255) / 256, 256>>>(pgx1b, b_hh1 + G_, plastb);

    // 7) FC head
    fc_kernel<<<B_, 256>>>(ph, plastb, fc_w, fc_b, out);
}

// round 5
// speedup vs baseline: 2.3904x; 1.7421x over previous
#include <cuda_runtime.h>
#include <cuda_bf16.h>
#include <cstdint>

#define B_  512
#define T_  64
#define H_  512
#define G_  1536
#define KP0 320

// ---------------- scratch ----------------------------------------------------
__device__ float g_gx0 [(size_t)B_ * T_ * 2 * G_];
__device__ float g_gx1 [(size_t)B_ * T_ * G_];
__device__ float g_gx1b[(size_t)B_ * G_];
__device__ float g_h   [2 * 2 * B_ * H_];            // fp32 ping-pong [buf][dir][B][H]
__device__ float g_lastb[(size_t)B_ * H_];
__device__ __align__(16) __nv_bfloat16 g_hhi [2 * 2 * B_ * H_];
__device__ __align__(16) __nv_bfloat16 g_hlo [2 * 2 * B_ * H_];
__device__ __align__(16) __nv_bfloat16 g_a0hi[(size_t)B_ * T_ * KP0];
__device__ __align__(16) __nv_bfloat16 g_a0lo[(size_t)B_ * T_ * KP0];
__device__ __align__(16) __nv_bfloat16 g_w0hi[(size_t)2 * G_ * KP0];
__device__ __align__(16) __nv_bfloat16 g_w0lo[(size_t)2 * G_ * KP0];
__device__ __align__(16) __nv_bfloat16 g_a1hi[(size_t)B_ * T_ * 2 * H_];  // = y hist
__device__ __align__(16) __nv_bfloat16 g_a1lo[(size_t)B_ * T_ * 2 * H_];
__device__ __align__(16) __nv_bfloat16 g_w1hi[(size_t)2 * G_ * 2 * H_];
__device__ __align__(16) __nv_bfloat16 g_w1lo[(size_t)2 * G_ * 2 * H_];
__device__ __align__(16) __nv_bfloat16 g_wh0hi[(size_t)2 * G_ * H_];
__device__ __align__(16) __nv_bfloat16 g_wh0lo[(size_t)2 * G_ * H_];
__device__ __align__(16) __nv_bfloat16 g_wh1hi[(size_t)2 * G_ * H_];
__device__ __align__(16) __nv_bfloat16 g_wh1lo[(size_t)2 * G_ * H_];

// ---------------- baseline-PTX helpers --------------------------------------
__device__ __forceinline__ uint32_t smem_u32(const void* p) {
    uint32_t a;
    asm("{ .reg .u64 t; cvta.to.shared.u64 t, %1; cvt.u32.u64 %0, t; }" : "=r"(a) : "l"(p));
    return a;
}
#define CP16(sm, gp)  asm volatile("cp.async.cg.shared.global [%0], [%1], 16;" :: "r"(sm), "l"(gp))
#define CP_COMMIT()   asm volatile("cp.async.commit_group;" ::: "memory")
#define CP_WAIT(n)    asm volatile("cp.async.wait_group %0;" :: "n"(n) : "memory")

__device__ __forceinline__ void ldsm4(uint32_t* r, uint32_t a) {
    asm volatile("ldmatrix.sync.aligned.m8n8.x4.shared.b16 {%0,%1,%2,%3}, [%4];"
        : "=r"(r[0]), "=r"(r[1]), "=r"(r[2]), "=r"(r[3]) : "r"(a));
}
__device__ __forceinline__ void ldsm2(uint32_t* r, uint32_t a) {
    asm volatile("ldmatrix.sync.aligned.m8n8.x2.shared.b16 {%0,%1}, [%2];"
        : "=r"(r[0]), "=r"(r[1]) : "r"(a));
}
__device__ __forceinline__ void mma16816(float* c, const uint32_t* a, const uint32_t* b) {
    asm volatile("mma.sync.aligned.m16n8k16.row.col.f32.bf16.bf16.f32 "
        "{%0,%1,%2,%3},{%4,%5,%6,%7},{%8,%9},{%0,%1,%2,%3};"
        : "+f"(c[0]), "+f"(c[1]), "+f"(c[2]), "+f"(c[3])
        : "r"(a[0]), "r"(a[1]), "r"(a[2]), "r"(a[3]), "r"(b[0]), "r"(b[1]));
}
__device__ __forceinline__ float sigm(float x) { return __fdividef(1.f, 1.f + __expf(-x)); }
__device__ __forceinline__ float tanh_(float x) { return 2.f * sigm(2.f * x) - 1.f; }

// ---------------- split / utility kernels -----------------------------------
__global__ void embed_split_kernel(const int* __restrict__ tokens,
                                   const float* __restrict__ emb,
                                   __nv_bfloat16* __restrict__ hi,
                                   __nv_bfloat16* __restrict__ lo)
{
    const int blk = blockIdx.x;
    const int t = blk / B_;
    const int b = blk - t * B_;
    const int tok = tokens[b * T_ + t];
    const float* src = emb + (size_t)tok * 300;
    size_t dst = (size_t)blk * KP0;
    for (int e = threadIdx.x; e < KP0; e += blockDim.x) {
        float v = (e < 300) ? src[e] : 0.f;
        __nv_bfloat16 h = __float2bfloat16(v);
        hi[dst + e] = h;
        lo[dst + e] = __float2bfloat16(v - __bfloat162float(h));
    }
}

__global__ void split_pad_kernel(const float* __restrict__ src,
                                 __nv_bfloat16* __restrict__ hi,
                                 __nv_bfloat16* __restrict__ lo,
                                 int rows, int K, int Kp)
{
    size_t idx = (size_t)blockIdx.x * blockDim.x + threadIdx.x;
    if (idx >= (size_t)rows * Kp) return;
    int r = (int)(idx / Kp);
    int c = (int)(idx - (size_t)r * Kp);
    float v = (c < K) ? src[(size_t)r * K + c] : 0.f;
    __nv_bfloat16 h = __float2bfloat16(v);
    hi[idx] = h;
    lo[idx] = __float2bfloat16(v - __bfloat162float(h));
}

__global__ void zero_kernel(float* __restrict__ p, int n)
{
    int i = blockIdx.x * blockDim.x + threadIdx.x;
    if (i < n) p[i] = 0.f;
}
__global__ void zero_bf_kernel(__nv_bfloat16* __restrict__ p, int n)
{
    int i = blockIdx.x * blockDim.x + threadIdx.x;
    if (i < n) p[i] = __float2bfloat16(0.f);
}

// ---------------- warp-MMA bf16-split GEMM (input GEMMs; round-4 proven) ---
#define SSTR 80
#define TILE_B (128 * SSTR)
#define STAGE_B (4 * TILE_B)
__global__ void __launch_bounds__(256, 1)
gemm_mma_split(const __nv_bfloat16* __restrict__ Ahi,
               const __nv_bfloat16* __restrict__ Alo,
               const __nv_bfloat16* __restrict__ Whi,
               const __nv_bfloat16* __restrict__ Wlo,
               const float* __restrict__ bias,
               float* __restrict__ C, int N, int Kp)
{
    extern __shared__ __align__(16) char smem[];
    const int tid = threadIdx.x;
    const int lane = tid & 31;
    const int wid = tid >> 5;
    const int wm = wid & 1;
    const int wn = wid >> 1;
    const int m0c = blockIdx.y * 128;
    const int n0c = blockIdx.x * 128;
    const int nchunks = Kp >> 5;
    const uint32_t sbase = smem_u32(smem);
    const __nv_bfloat16* bases[4] = { Ahi, Alo, Whi, Wlo };

    auto load_chunk = [&](int c, int s) {
        const uint32_t st = sbase + s * STAGE_B;
        #pragma unroll
        for (int q = 0; q < 8; q++) {
            int g = tid + q * 256;
            int tile = g >> 9;
            int p = g & 511;
            int r = p >> 2, seg = p & 3;
            int rowbase = (tile < 2) ? m0c : n0c;
            const __nv_bfloat16* gp =
                bases[tile] + (size_t)(rowbase + r) * Kp + c * 32 + seg * 8;
            CP16(st + tile * TILE_B + r * SSTR + seg * 16, gp);
        }
        CP_COMMIT();
    };

    float acc[16][4];
    #pragma unroll
    for (int i = 0; i < 16; i++)
        #pragma unroll
        for (int j = 0; j < 4; j++) acc[i][j] = 0.f;

    load_chunk(0, 0);
    for (int c = 0; c < nchunks; c++) {
        const int s = c & 1;
        if (c + 1 < nchunks) { load_chunk(c + 1, s ^ 1); CP_WAIT(1); }
        else                 { CP_WAIT(0); }
        __syncthreads();
        const uint32_t st = sbase + s * STAGE_B;
        #pragma unroll
        for (int kk = 0; kk < 2; kk++) {
            uint32_t ahi[4][4], alo[4][4], bhi[4][2], blo[4][2];
            #pragma unroll
            for (int i = 0; i < 4; i++) {
                int row = wm * 64 + i * 16 + (lane & 15);
                uint32_t off = row * SSTR + kk * 32 + (lane >> 4) * 16;
                ldsm4(ahi[i], st + off);
                ldsm4(alo[i], st + TILE_B + off);
            }
            #pragma unroll
            for (int j = 0; j < 4; j++) {
                int row = wn * 32 + j * 8 + (lane & 7);
                uint32_t off = row * SSTR + kk * 32 + ((lane >> 3) & 1) * 16;
                ldsm2(bhi[j], st + 2 * TILE_B + off);
                ldsm2(blo[j], st + 3 * TILE_B + off);
            }
            #pragma unroll
            for (int i = 0; i < 4; i++)
                #pragma unroll
                for (int j = 0; j < 4; j++) {
                    mma16816(acc[i * 4 + j], ahi[i], bhi[j]);
                    mma16816(acc[i * 4 + j], ahi[i], blo[j]);
                    mma16816(acc[i * 4 + j], alo[i], bhi[j]);
                }
        }
        __syncthreads();
    }
    #pragma unroll
    for (int i = 0; i < 4; i++) {
        int m = m0c + wm * 64 + i * 16 + (lane >> 2);
        #pragma unroll
        for (int j = 0; j < 4; j++) {
            int n = n0c + wn * 32 + j * 8 + (lane & 3) * 2;
            float b0 = bias[n], b1 = bias[n + 1];
            float* a = acc[i * 4 + j];
            float2 v0 = { a[0] + b0, a[1] + b1 };
            float2 v1 = { a[2] + b0, a[3] + b1 };
            *reinterpret_cast<float2*>(C + (size_t)m * N + n) = v0;
            *reinterpret_cast<float2*>(C + (size_t)(m + 8) * N + n) = v1;
        }
    }
}

// ---------------- fused tensor-core GRU step --------------------------------
// gh = h_prev @ Whh^T (hi/lo split, 3 passes) + gates, one kernel per step.
// CTA: 64 batch x JT j-units x 3 gates.  JT = 32*NJF.  Warps 2m x 4n.
// Warp n-tile = (8*NJF j's) x 3 gates -> same-thread r/z/n accumulators.
template<int NJF>
__global__ void __launch_bounds__(256, 1)
gru_step_mma(const float* __restrict__ h_prev,
             const __nv_bfloat16* __restrict__ hp_hi,
             const __nv_bfloat16* __restrict__ hp_lo,
             float* __restrict__ h_next,
             __nv_bfloat16* __restrict__ hn_hi,
             __nv_bfloat16* __restrict__ hn_lo,
             const float* __restrict__ gx, int gx_ld, int gx_ds,
             const __nv_bfloat16* __restrict__ whh_hi,
             const __nv_bfloat16* __restrict__ whh_lo,
             const float* __restrict__ bhh,
             __nv_bfloat16* __restrict__ y_hi,
             __nv_bfloat16* __restrict__ y_lo,
             int s)
{
    constexpr int JT = 32 * NJF;
    constexpr int WROWS = 3 * JT;
    constexpr int A_B = 64 * SSTR;                 // bytes per A tile (64 x 32 bf16)
    constexpr int W_B = WROWS * SSTR;
    constexpr int STG = 2 * A_B + 2 * W_B;
    constexpr int NPC = 2 * 64 * 4 + 2 * WROWS * 4;  // cp16 pieces per chunk
    constexpr int SH = (NJF == 2) ? 6 : 5;           // log2(JT)

    extern __shared__ __align__(16) char smem[];
    const int tid = threadIdx.x;
    const int lane = tid & 31;
    const int wid = tid >> 5;
    const int wm = wid & 1;
    const int wn = wid >> 1;
    const int d  = blockIdx.z;
    const int b0 = blockIdx.x * 64;
    const int j0 = blockIdx.y * JT;
    const int t  = (d == 0) ? s : (T_ - 1 - s);
    const uint32_t sb = smem_u32(smem);

    const __nv_bfloat16* Ah = hp_hi + (size_t)d * B_ * H_;
    const __nv_bfloat16* Al = hp_lo + (size_t)d * B_ * H_;
    const __nv_bfloat16* Wh = whh_hi + (size_t)d * G_ * H_;
    const __nv_bfloat16* Wl = whh_lo + (size_t)d * G_ * H_;

    auto load_chunk = [&](int c, int st) {
        const uint32_t base = sb + st * STG;
        #pragma unroll
        for (int q = 0; q < NPC / 256; q++) {
            int g = tid + q * 256;
            uint32_t soff;
            const __nv_bfloat16* gp;
            if (g < 512) {
                int ishi = (g < 256);
                int p = g & 255;
                int r = p >> 2, seg = p & 3;
                gp = (ishi ? Ah : Al) + (size_t)(b0 + r) * H_ + c * 32 + seg * 8;
                soff = base + (ishi ? 0 : A_B) + r * SSTR + seg * 16;
            } else {
                int gw = g - 512;
                int ishi = (gw < WROWS * 4);
                int p = ishi ? gw : gw - WROWS * 4;
                int r = p >> 2, seg = p & 3;
                int grow = ((r >> SH) << 9) + j0 + (r & (JT - 1));
                gp = (ishi ? Wh : Wl) + (size_t)grow * H_ + c * 32 + seg * 8;
                soff = base + 2 * A_B + (ishi ? 0 : W_B) + r * SSTR + seg * 16;
            }
            CP16(soff, gp);
        }
        CP_COMMIT();
    };

    float acc[3][2][NJF][4];
    #pragma unroll
    for (int g = 0; g < 3; g++)
        #pragma unroll
        for (int i = 0; i < 2; i++)
            #pragma unroll
            for (int jf = 0; jf < NJF; jf++)
                #pragma unroll
                for (int r = 0; r < 4; r++) acc[g][i][jf][r] = 0.f;

    load_chunk(0, 0);
    for (int c = 0; c < H_ / 32; c++) {
        const int st = c & 1;
        if (c + 1 < H_ / 32) { load_chunk(c + 1, st ^ 1); CP_WAIT(1); }
        else                 { CP_WAIT(0); }
        __syncthreads();
        const uint32_t base = sb + st * STG;
        #pragma unroll
        for (int kk = 0; kk < 2; kk++) {
            uint32_t ah[2][4], al[2][4];
            #pragma unroll
            for (int i = 0; i < 2; i++) {
                int row = wm * 32 + i * 16 + (lane & 15);
                uint32_t off = row * SSTR + kk * 32 + (lane >> 4) * 16;
                ldsm4(ah[i], base + off);
                ldsm4(al[i], base + A_B + off);
            }
            uint32_t bh[3][NJF][2], bl[3][NJF][2];
            #pragma unroll
            for (int g = 0; g < 3; g++)
                #pragma unroll
                for (int jf = 0; jf < NJF; jf++) {
                    int row = g * JT + wn * 8 * NJF + jf * 8 + (lane & 7);
                    uint32_t off = row * SSTR + kk * 32 + ((lane >> 3) & 1) * 16;
                    ldsm2(bh[g][jf], base + 2 * A_B + off);
                    ldsm2(bl[g][jf], base + 2 * A_B + W_B + off);
                }
            #pragma unroll
            for (int g = 0; g < 3; g++)
                #pragma unroll
                for (int i = 0; i < 2; i++)
                    #pragma unroll
                    for (int jf = 0; jf < NJF; jf++) {
                        mma16816(acc[g][i][jf], ah[i], bh[g][jf]);
                        mma16816(acc[g][i][jf], ah[i], bl[g][jf]);
                        mma16816(acc[g][i][jf], al[i], bh[g][jf]);
                    }
        }
        __syncthreads();
    }

    // -------- gate epilogue (register-local r/z/n) --------
    const float* bhh_d = bhh + d * G_;
    #pragma unroll
    for (int i = 0; i < 2; i++)
        #pragma unroll
        for (int jf = 0; jf < NJF; jf++)
            #pragma unroll
            for (int half = 0; half < 2; half++) {
                int b = b0 + wm * 32 + i * 16 + (lane >> 2) + half * 8;
                size_t row = (size_t)t * B_ + b;
                const float* gxr = gx + row * gx_ld + (size_t)d * gx_ds;
                const float* hpr = h_prev + ((size_t)d * B_ + b) * H_;
                int jc = j0 + wn * 8 * NJF + jf * 8 + (lane & 3) * 2;
                #pragma unroll
                for (int e = 0; e < 2; e++) {
                    int j = jc + e;
                    float ghr = acc[0][i][jf][half * 2 + e] + bhh_d[j];
                    float ghz = acc[1][i][jf][half * 2 + e] + bhh_d[H_ + j];
                    float ghn = acc[2][i][jf][half * 2 + e] + bhh_d[2 * H_ + j];
                    float rg = sigm(gxr[j] + ghr);
                    float zg = sigm(gxr[H_ + j] + ghz);
                    float ng = tanh_(gxr[2 * H_ + j] + rg * ghn);
                    float hn = (1.f - zg) * ng + zg * hpr[j];
                    size_t ho = ((size_t)d * B_ + b) * H_ + j;
                    h_next[ho] = hn;
                    __nv_bfloat16 hib = __float2bfloat16(hn);
                    __nv_bfloat16 lob = __float2bfloat16(hn - __bfloat162float(hib));
                    hn_hi[ho] = hib;
                    hn_lo[ho] = lob;
                    if (y_hi) {
                        size_t yo = row * (size_t)(2 * H_) + (size_t)d * H_ + j;
                        y_hi[yo] = hib;
                        y_lo[yo] = lob;
                    }
                }
            }
}

// ---------------- layer-1 backward single step + FC head --------------------
__global__ void bwd1_gates(const float* __restrict__ gxb,
                           const float* __restrict__ bhh,
                           float* __restrict__ out)
{
    int idx = blockIdx.x * blockDim.x + threadIdx.x;
    if (idx >= B_ * H_) return;
    int b = idx >> 9, j = idx & 511;
    const float* r0 = gxb + (size_t)b * G_;
    float rg = sigm(r0[j] + bhh[j]);
    float zg = sigm(r0[H_ + j] + bhh[H_ + j]);
    float ng = tanh_(r0[2 * H_ + j] + rg * bhh[2 * H_ + j]);
    out[idx] = (1.f - zg) * ng;
}

__global__ void fc_kernel(const float* __restrict__ hf, const float* __restrict__ hb,
                          const float* __restrict__ fcw, const float* __restrict__ fcb,
                          float* __restrict__ out)
{
    int b = blockIdx.x, tid = threadIdx.x;
    float s0 = 0.f, s1 = 0.f;
    for (int j = tid; j < 1024; j += 256) {
        float v = (j < 512) ? hf[(size_t)b * 512 + j] : hb[(size_t)b * 512 + (j - 512)];
        s0 += v * fcw[j];
        s1 += v * fcw[1024 + j];
    }
    __shared__ float red0[256], red1[256];
    red0[tid] = s0; red1[tid] = s1;
    __syncthreads();
    for (int off = 128; off > 0; off >>= 1) {
        if (tid < off) { red0[tid] += red0[tid + off]; red1[tid] += red1[tid + off]; }
        __syncthreads();
    }
    if (tid == 0) {
        out[b * 2 + 0] = red0[0] + fcb[0];
        out[b * 2 + 1] = red1[0] + fcb[1];
    }
}

// ---------------- launch -----------------------------------------------------
extern "C" void kernel_launch(void* const* d_in, const int* in_sizes, int n_in,
                              void* d_out, int out_size)
{
    (void)in_sizes; (void)n_in; (void)out_size;
    const int*   tokens = (const int*)  d_in[0];
    const float* emb    = (const float*)d_in[1];
    const float* w_ih0  = (const float*)d_in[2];
    const float* w_hh0  = (const float*)d_in[3];
    const float* b_ih0  = (const float*)d_in[4];
    const float* b_hh0  = (const float*)d_in[5];
    const float* w_ih1  = (const float*)d_in[6];
    const float* w_hh1  = (const float*)d_in[7];
    const float* b_ih1  = (const float*)d_in[8];
    const float* b_hh1  = (const float*)d_in[9];
    const float* fc_w   = (const float*)d_in[10];
    const float* fc_b   = (const float*)d_in[11];
    float* out = (float*)d_out;

    float *pgx0, *pgx1, *pgx1b, *ph, *plastb;
    cudaGetSymbolAddress((void**)&pgx0,   g_gx0);
    cudaGetSymbolAddress((void**)&pgx1,   g_gx1);
    cudaGetSymbolAddress((void**)&pgx1b,  g_gx1b);
    cudaGetSymbolAddress((void**)&ph,     g_h);
    cudaGetSymbolAddress((void**)&plastb, g_lastb);
    __nv_bfloat16 *phhi, *phlo, *pa0hi, *pa0lo, *pw0hi, *pw0lo;
    __nv_bfloat16 *pa1hi, *pa1lo, *pw1hi, *pw1lo, *pwh0hi, *pwh0lo, *pwh1hi, *pwh1lo;
    cudaGetSymbolAddress((void**)&phhi,  g_hhi);
    cudaGetSymbolAddress((void**)&phlo,  g_hlo);
    cudaGetSymbolAddress((void**)&pa0hi, g_a0hi);
    cudaGetSymbolAddress((void**)&pa0lo, g_a0lo);
    cudaGetSymbolAddress((void**)&pw0hi, g_w0hi);
    cudaGetSymbolAddress((void**)&pw0lo, g_w0lo);
    cudaGetSymbolAddress((void**)&pa1hi, g_a1hi);
    cudaGetSymbolAddress((void**)&pa1lo, g_a1lo);
    cudaGetSymbolAddress((void**)&pw1hi, g_w1hi);
    cudaGetSymbolAddress((void**)&pw1lo, g_w1lo);
    cudaGetSymbolAddress((void**)&pwh0hi, g_wh0hi);
    cudaGetSymbolAddress((void**)&pwh0lo, g_wh0lo);
    cudaGetSymbolAddress((void**)&pwh1hi, g_wh1hi);
    cudaGetSymbolAddress((void**)&pwh1lo, g_wh1lo);

    const int GSM = 2 * STAGE_B;                   // 81920 (input GEMM)
    const int SSM2 = 2 * (2 * 64 * SSTR + 2 * 192 * SSTR);  // 81920 (NJF=2)
    const int SSM1 = 2 * (2 * 64 * SSTR + 2 * 96 * SSTR);   // 51200 (NJF=1)
    cudaFuncSetAttribute(gemm_mma_split, cudaFuncAttributeMaxDynamicSharedMemorySize, GSM);
    cudaFuncSetAttribute(gru_step_mma<2>, cudaFuncAttributeMaxDynamicSharedMemorySize, SSM2);
    cudaFuncSetAttribute(gru_step_mma<1>, cudaFuncAttributeMaxDynamicSharedMemorySize, SSM1);

    const size_t HB = (size_t)2 * B_ * H_;         // elems per ping-pong buffer
    const int MT = B_ * T_;

    // 1) embed + weight splits
    embed_split_kernel<<<MT, 128>>>(tokens, emb, pa0hi, pa0lo);
    split_pad_kernel<<<(2 * G_ * KP0 + 255) / 256, 256>>>(w_ih0, pw0hi, pw0lo, 2 * G_, 300, KP0);
    split_pad_kernel<<<(int)(((size_t)2 * G_ * 1024 + 255) / 256), 256>>>(w_ih1, pw1hi, pw1lo, 2 * G_, 1024, 1024);
    split_pad_kernel<<<(2 * G_ * H_ + 255) / 256, 256>>>(w_hh0, pwh0hi, pwh0lo, 2 * G_, H_, H_);
    split_pad_kernel<<<(2 * G_ * H_ + 255) / 256, 256>>>(w_hh1, pwh1hi, pwh1lo, 2 * G_, H_, H_);
    zero_kernel<<<(int)(2 * HB + 255) / 256, 256>>>(ph, (int)(2 * HB));
    zero_bf_kernel<<<(int)(2 * HB + 255) / 256, 256>>>(phhi, (int)(2 * HB));
    zero_bf_kernel<<<(int)(2 * HB + 255) / 256, 256>>>(phlo, (int)(2 * HB));

    // 2) layer0 input GEMM: gx0[32768][3072]
    gemm_mma_split<<<dim3(2 * G_ / 128, MT / 128), 256, GSM>>>(
        pa0hi, pa0lo, pw0hi, pw0lo, b_ih0, pgx0, 2 * G_, KP0);

    // 3) layer0 bidirectional scan (tensor cores, writes y hist as hi/lo)
    for (int s = 0; s < T_; s++) {
        int pb = s & 1;
        gru_step_mma<2><<<dim3(B_ / 64, H_ / 64, 2), 256, SSM2>>>(
            ph + pb * HB, phhi + pb * HB, phlo + pb * HB,
            ph + (pb ^ 1) * HB, phhi + (pb ^ 1) * HB, phlo + (pb ^ 1) * HB,
            pgx0, 2 * G_, G_, pwh0hi, pwh0lo, b_hh0, pa1hi, pa1lo, s);
    }

    // 4) layer1 fwd input GEMM (consumes y hist hi/lo directly)
    gemm_mma_split<<<dim3(G_ / 128, MT / 128), 256, GSM>>>(
        pa1hi, pa1lo, pw1hi, pw1lo, b_ih1, pgx1, G_, 1024);

    // 5) layer1 forward scan
    zero_kernel<<<(int)(2 * HB + 255) / 256, 256>>>(ph, (int)(2 * HB));
    zero_bf_kernel<<<(int)(2 * HB + 255) / 256, 256>>>(phhi, (int)(2 * HB));
    zero_bf_kernel<<<(int)(2 * HB + 255) / 256, 256>>>(phlo, (int)(2 * HB));
    for (int s = 0; s < T_; s++) {
        int pb = s & 1;
        gru_step_mma<1><<<dim3(B_ / 64, H_ / 32, 1), 256, SSM1>>>(
            ph + pb * HB, phhi + pb * HB, phlo + pb * HB,
            ph + (pb ^ 1) * HB, phhi + (pb ^ 1) * HB, phlo + (pb ^ 1) * HB,
            pgx1, G_, 0, pwh1hi, pwh1lo, b_hh1,
            (__nv_bfloat16*)nullptr, (__nv_bfloat16*)nullptr, s);
    }
    // final fwd hidden in buffer 0, dir 0

    // 6) layer1 backward = ONE step at t=T-1 (h0=0)
    gemm_mma_split<<<dim3(G_ / 128, B_ / 128), 256, GSM>>>(
        pa1hi + (size_t)(T_ - 1) * B_ * 1024, pa1lo + (size_t)(T_ - 1) * B_ * 1024,
        pw1hi + (size_t)G_ * 1024, pw1lo + (size_t)G_ * 1024,
        b_ih1 + G_, pgx1b, G_, 1024);
    bwd1_gates<<<(B_ * H_ + 255) / 256, 256>>>(pgx1b, b_hh1 + G_, plastb);

    // 7) FC head
    fc_kernel<<<B_, 256>>>(ph, plastb, fc_w, fc_b, out);
}